// round 5
// baseline (speedup 1.0000x reference)
#include <cuda_runtime.h>

#define B_   4096
#define T_   200
#define S_   20
#define NF_  16
#define NT_  2
#define H1_  128
#define H2_  64
#define H3_  32
#define BT_  32
#define NBLK 128
#define NTH  256

// ---- smem layout (float offsets); row stride 36 (144B, 16B aligned) ----
#define ROW 36
#define XB  0                       // x: [16][36]              = 576
#define H1B 576                     // h1: 2 x [128][36]        = 9216
#define H2B 9792                    // h2: 2 x [64][36]         = 4608
#define DSO 14400                   // dense: [32][33]          = 1056
#define SMF 15456
#define SMB (SMF * 4)               // 61824 B

// ---- prepped weights ----
__device__ float4 d_W1v[144 * 128]; // [k][u] = gates (i,f,g,o) of unit u, col k
__device__ float4 d_W2v[192 * 64];
__device__ float4 d_b1v[128];
__device__ float4 d_b2v[64];

typedef unsigned long long u64;

__device__ __forceinline__ u64 pack2(float lo, float hi) {
    u64 r; asm("mov.b64 %0, {%1, %2};" : "=l"(r) : "f"(lo), "f"(hi)); return r;
}
__device__ __forceinline__ void unpack2(u64 v, float& lo, float& hi) {
    asm("mov.b64 {%0, %1}, %2;" : "=f"(lo), "=f"(hi) : "l"(v));
}
__device__ __forceinline__ u64 fma2(u64 a, u64 b, u64 c) {
    u64 d; asm("fma.rn.f32x2 %0, %1, %2, %3;" : "=l"(d) : "l"(a), "l"(b), "l"(c)); return d;
}
__device__ __forceinline__ float tanhf_(float x) {
    float y; asm("tanh.approx.f32 %0, %1;" : "=f"(y) : "f"(x)); return y;
}
__device__ __forceinline__ float sigmoidf_(float x) {
    return fmaf(0.5f, tanhf_(0.5f * x), 0.5f);
}

// 4 gates x 8 batches for one unit, one k
__device__ __forceinline__ void mac4(u64* acc, float4 wv, u64 h0, u64 h1, u64 h2, u64 h3) {
    u64 wi = pack2(wv.x, wv.x), wf = pack2(wv.y, wv.y);
    u64 wg = pack2(wv.z, wv.z), wo = pack2(wv.w, wv.w);
    acc[0]  = fma2(wi, h0, acc[0]);  acc[1]  = fma2(wi, h1, acc[1]);
    acc[2]  = fma2(wi, h2, acc[2]);  acc[3]  = fma2(wi, h3, acc[3]);
    acc[4]  = fma2(wf, h0, acc[4]);  acc[5]  = fma2(wf, h1, acc[5]);
    acc[6]  = fma2(wf, h2, acc[6]);  acc[7]  = fma2(wf, h3, acc[7]);
    acc[8]  = fma2(wg, h0, acc[8]);  acc[9]  = fma2(wg, h1, acc[9]);
    acc[10] = fma2(wg, h2, acc[10]); acc[11] = fma2(wg, h3, acc[11]);
    acc[12] = fma2(wo, h0, acc[12]); acc[13] = fma2(wo, h1, acc[13]);
    acc[14] = fma2(wo, h2, acc[14]); acc[15] = fma2(wo, h3, acc[15]);
}

__device__ __forceinline__ void acc_init(u64* acc, float4 bv) {
    u64 bi = pack2(bv.x, bv.x), bf = pack2(bv.y, bv.y);
    u64 bg = pack2(bv.z, bv.z), bo = pack2(bv.w, bv.w);
#pragma unroll
    for (int j = 0; j < 4; j++) { acc[j] = bi; acc[4+j] = bf; acc[8+j] = bg; acc[12+j] = bo; }
}

// pointwise for one unit, 8 batches: gates in acc (i,f,g,o x 4 pairs), c in cr[8]
__device__ __forceinline__ void pw_unit(const u64* acc, float* cr, float* dst) {
    float hv[8];
#pragma unroll
    for (int j = 0; j < 4; j++) {
        float i0, i1, f0, f1, g0, g1, o0, o1;
        unpack2(acc[j],    i0, i1); unpack2(acc[4+j],  f0, f1);
        unpack2(acc[8+j],  g0, g1); unpack2(acc[12+j], o0, o1);
        float c0 = sigmoidf_(f0) * cr[2*j]   + sigmoidf_(i0) * tanhf_(g0);
        float c1 = sigmoidf_(f1) * cr[2*j+1] + sigmoidf_(i1) * tanhf_(g1);
        cr[2*j] = c0; cr[2*j+1] = c1;
        hv[2*j]   = sigmoidf_(o0) * tanhf_(c0);
        hv[2*j+1] = sigmoidf_(o1) * tanhf_(c1);
    }
    *(float4*)dst       = make_float4(hv[0], hv[1], hv[2], hv[3]);
    *(float4*)(dst + 4) = make_float4(hv[4], hv[5], hv[6], hv[7]);
}

// ---- layer 1: thread = units (2up, 2up+1) x batches 8bg..8bg+7 ----
__device__ __forceinline__ void layer1(float* sm, int up, int bg, int p, float* c1r) {
    u64 accA[16], accB[16];
    acc_init(accA, d_b1v[2*up]);
    acc_init(accB, d_b1v[2*up + 1]);
    const float4* __restrict__ w = d_W1v + 2*up;
    const float* xrow = sm + XB + 8*bg;
#pragma unroll 4
    for (int k = 0; k < NF_; k++) {
        ulonglong2 hA = *(const ulonglong2*)(xrow + k*ROW);
        ulonglong2 hB = *(const ulonglong2*)(xrow + k*ROW + 4);
        float4 wA = w[k*128], wB = w[k*128 + 1];
        mac4(accA, wA, hA.x, hA.y, hB.x, hB.y);
        mac4(accB, wB, hA.x, hA.y, hB.x, hB.y);
    }
    const float* hrow = sm + H1B + p*4608 + 8*bg;
    const float4* __restrict__ wh = w + NF_*128;
#pragma unroll 4
    for (int k = 0; k < H1_; k++) {
        ulonglong2 hA = *(const ulonglong2*)(hrow + k*ROW);
        ulonglong2 hB = *(const ulonglong2*)(hrow + k*ROW + 4);
        float4 wA = wh[k*128], wB = wh[k*128 + 1];
        mac4(accA, wA, hA.x, hA.y, hB.x, hB.y);
        mac4(accB, wB, hA.x, hA.y, hB.x, hB.y);
    }
    float* dst = sm + H1B + (p^1)*4608 + (2*up)*ROW + 8*bg;
    pw_unit(accA, c1r,     dst);
    pw_unit(accB, c1r + 8, dst + ROW);
}

// ---- layer 2: thread = unit u2 x batches 8bg..8bg+7 ----
__device__ __forceinline__ void layer2(float* sm, int u2, int bg, int p, float* c2r) {
    u64 acc[16];
    acc_init(acc, d_b2v[u2]);
    const float4* __restrict__ w = d_W2v + u2;
    const float* h1n = sm + H1B + (p^1)*4608 + 8*bg;
#pragma unroll 4
    for (int k = 0; k < H1_; k++) {
        ulonglong2 hA = *(const ulonglong2*)(h1n + k*ROW);
        ulonglong2 hB = *(const ulonglong2*)(h1n + k*ROW + 4);
        mac4(acc, w[k*64], hA.x, hA.y, hB.x, hB.y);
    }
    const float* h2r = sm + H2B + p*2304 + 8*bg;
#pragma unroll 4
    for (int k = 0; k < H2_; k++) {
        ulonglong2 hA = *(const ulonglong2*)(h2r + k*ROW);
        ulonglong2 hB = *(const ulonglong2*)(h2r + k*ROW + 4);
        mac4(acc, w[(H1_+k)*64], hA.x, hA.y, hB.x, hB.y);
    }
    pw_unit(acc, c2r, sm + H2B + (p^1)*2304 + u2*ROW + 8*bg);
}

// ---- weight prep ----
__global__ void prep_kernel(const float* __restrict__ Wih1, const float* __restrict__ Whh1,
                            const float* __restrict__ bih1, const float* __restrict__ bhh1,
                            const float* __restrict__ Wih2, const float* __restrict__ Whh2,
                            const float* __restrict__ bih2, const float* __restrict__ bhh2) {
    int idx = blockIdx.x * blockDim.x + threadIdx.x;
    int stride = gridDim.x * blockDim.x;
    for (int i = idx; i < 144*128; i += stride) {
        int k = i >> 7, u = i & 127;
        float4 v;
        if (k < NF_) {
            v = make_float4(Wih1[u*NF_ + k], Wih1[(H1_+u)*NF_ + k],
                            Wih1[(2*H1_+u)*NF_ + k], Wih1[(3*H1_+u)*NF_ + k]);
        } else {
            int kk = k - NF_;
            v = make_float4(Whh1[u*H1_ + kk], Whh1[(H1_+u)*H1_ + kk],
                            Whh1[(2*H1_+u)*H1_ + kk], Whh1[(3*H1_+u)*H1_ + kk]);
        }
        d_W1v[i] = v;
    }
    for (int i = idx; i < 192*64; i += stride) {
        int k = i >> 6, u = i & 63;
        float4 v;
        if (k < H1_) {
            v = make_float4(Wih2[u*H1_ + k], Wih2[(H2_+u)*H1_ + k],
                            Wih2[(2*H2_+u)*H1_ + k], Wih2[(3*H2_+u)*H1_ + k]);
        } else {
            int kk = k - H1_;
            v = make_float4(Whh2[u*H2_ + kk], Whh2[(H2_+u)*H2_ + kk],
                            Whh2[(2*H2_+u)*H2_ + kk], Whh2[(3*H2_+u)*H2_ + kk]);
        }
        d_W2v[i] = v;
    }
    if (idx < H1_)
        d_b1v[idx] = make_float4(bih1[idx] + bhh1[idx], bih1[H1_+idx] + bhh1[H1_+idx],
                                 bih1[2*H1_+idx] + bhh1[2*H1_+idx], bih1[3*H1_+idx] + bhh1[3*H1_+idx]);
    if (idx < H2_)
        d_b2v[idx] = make_float4(bih2[idx] + bhh2[idx], bih2[H2_+idx] + bhh2[H2_+idx],
                                 bih2[2*H2_+idx] + bhh2[2*H2_+idx], bih2[3*H2_+idx] + bhh2[3*H2_+idx]);
}

// ---- main persistent kernel ----
__global__ void __launch_bounds__(NTH, 1) lstm_main(
    const float* __restrict__ xh, const float* __restrict__ xfut,
    const float* __restrict__ Wd, const float* __restrict__ bd,
    const float* __restrict__ Wf, const float* __restrict__ bf,
    const float* __restrict__ ob, float* __restrict__ out) {
    extern __shared__ float sm[];
    const int tid = threadIdx.x;
    const int b0  = blockIdx.x * BT_;
    const int up = tid & 63, bg = tid >> 6;   // layer1 map (also layer2: u2=up)

    for (int i = tid; i < SMF; i += NTH) sm[i] = 0.0f;

    float c1r[16], c2r[8];
#pragma unroll
    for (int j = 0; j < 16; j++) c1r[j] = 0.0f;
#pragma unroll
    for (int j = 0; j < 8; j++) c2r[j] = 0.0f;

    // load x_0
    {
        int f = tid >> 4, bt = tid & 15;
        sm[XB + f*ROW + bt]      = xh[(size_t)(b0 + bt)      * T_ * NF_ + f];
        sm[XB + f*ROW + bt + 16] = xh[(size_t)(b0 + bt + 16) * T_ * NF_ + f];
    }
    __syncthreads();

    int p = 0;
    // ---------- encoder ----------
    for (int t = 0; t < T_; t++) {
        layer1(sm, up, bg, p, c1r);
        __syncthreads();
        layer2(sm, up, bg, p, c2r);
        if (t < T_ - 1) {
            int f = tid >> 4, bt = tid & 15;
            sm[XB + f*ROW + bt]      = xh[(size_t)(b0 + bt)      * T_ * NF_ + (t+1)*NF_ + f];
            sm[XB + f*ROW + bt + 16] = xh[(size_t)(b0 + bt + 16) * T_ * NF_ + (t+1)*NF_ + f];
        }
        __syncthreads();
        p ^= 1;
    }
    // x buffer rows 14,15 still hold x_{T-1}[14:16] == initial cur.

    // load refs for st=0
    if (tid < 224) {
        int f = tid % 14, bt = tid / 14;
        sm[XB + f*ROW + bt]      = xfut[(size_t)(b0 + bt)      * S_ * 14 + f];
        sm[XB + f*ROW + bt + 16] = xfut[(size_t)(b0 + bt + 16) * S_ * 14 + f];
    }
    __syncthreads();

    // ---------- decoder ----------
    for (int st = 0; st < S_; st++) {
        layer1(sm, up, bg, p, c1r);
        __syncthreads();
        layer2(sm, up, bg, p, c2r);
        if (st < S_ - 1 && tid < 224) {
            int f = tid % 14, bt = tid / 14;
            sm[XB + f*ROW + bt]      = xfut[(size_t)(b0 + bt)      * S_ * 14 + (st+1)*14 + f];
            sm[XB + f*ROW + bt + 16] = xfut[(size_t)(b0 + bt + 16) * S_ * 14 + (st+1)*14 + f];
        }
        __syncthreads();

        // dense: DS[bt][du] = relu(h2_new @ Wd^T + bd)
        {
            int du = tid & 31, q = tid >> 5;   // q 0..7 -> batches q, q+8, q+16, q+24
            const float* h2n = sm + H2B + (p^1)*2304;
            float a0 = 0.f, a1 = 0.f, a2 = 0.f, a3 = 0.f;
#pragma unroll 4
            for (int k = 0; k < H2_; k++) {
                float wv = Wd[du*H2_ + k];
                const float* r = h2n + k*ROW;
                a0 = fmaf(wv, r[q],      a0);
                a1 = fmaf(wv, r[q + 8],  a1);
                a2 = fmaf(wv, r[q + 16], a2);
                a3 = fmaf(wv, r[q + 24], a3);
            }
            float bdv = bd[du];
            sm[DSO + q*33 + du]        = fmaxf(a0 + bdv, 0.f);
            sm[DSO + (q+8)*33 + du]    = fmaxf(a1 + bdv, 0.f);
            sm[DSO + (q+16)*33 + du]   = fmaxf(a2 + bdv, 0.f);
            sm[DSO + (q+24)*33 + du]   = fmaxf(a3 + bdv, 0.f);
        }
        __syncthreads();

        // pred + feedback
        if (tid < BT_ * NT_) {
            int bt = tid >> 1, tt = tid & 1;
            float acc = 0.f;
#pragma unroll
            for (int k = 0; k < H3_; k++)
                acc = fmaf(sm[DSO + bt*33 + k], Wf[tt*H3_ + k], acc);
            float pr = acc + bf[tt] + ob[tt];
            out[(size_t)(b0 + bt) * S_ * NT_ + st * NT_ + tt] = pr;
            sm[XB + (NF_ - NT_ + tt)*ROW + bt] = pr;
        }
        __syncthreads();
        p ^= 1;
    }
}

// ---- launch ----
extern "C" void kernel_launch(void* const* d_in, const int* in_sizes, int n_in,
                              void* d_out, int out_size) {
    (void)in_sizes; (void)n_in; (void)out_size;
    const float* xh   = (const float*)d_in[0];
    const float* xfut = (const float*)d_in[1];
    const float* Wih1 = (const float*)d_in[2];
    const float* Whh1 = (const float*)d_in[3];
    const float* bih1 = (const float*)d_in[4];
    const float* bhh1 = (const float*)d_in[5];
    const float* Wih2 = (const float*)d_in[6];
    const float* Whh2 = (const float*)d_in[7];
    const float* bih2 = (const float*)d_in[8];
    const float* bhh2 = (const float*)d_in[9];
    const float* Wd   = (const float*)d_in[10];
    const float* bd   = (const float*)d_in[11];
    const float* Wf   = (const float*)d_in[12];
    const float* bf   = (const float*)d_in[13];
    const float* ob   = (const float*)d_in[14];
    float* out = (float*)d_out;

    cudaFuncSetAttribute(lstm_main, cudaFuncAttributeMaxDynamicSharedMemorySize, SMB);
    prep_kernel<<<128, 256>>>(Wih1, Whh1, bih1, bhh1, Wih2, Whh2, bih2, bhh2);
    lstm_main<<<NBLK, NTH, SMB>>>(xh, xfut, Wd, bd, Wf, bf, ob, out);
}

// round 6
// speedup vs baseline: 1.2312x; 1.2312x over previous
#include <cuda_runtime.h>

#define B_   4096
#define T_   200
#define S_   20
#define NF_  16
#define NT_  2
#define H1_  128
#define H2_  64
#define H3_  32
#define BT_  16
#define NBLK (B_ / BT_)   // 256
#define NTH  256

// ---- smem layout (float offsets); row stride 20 (80B, 16B-aligned) ----
#define ROW 20
#define XB  0                        // x: [16][20]           = 320
#define H1B 320                      // h1: 2 x [128][20]     = 5120
#define H2B 5440                     // h2: 2 x [64][20]      = 2560
#define DSO 8000                     // dense: [16][33]       = 528
#define SMF 8528
#define SMB (SMF * 4)                // 34112 B -> 2 CTAs/SM

// ---- prepped weights: [k][u] = float4(gate i,f,g,o) ----
__device__ float4 d_W1v[144 * 128];
__device__ float4 d_W2v[192 * 64];
__device__ float4 d_b1v[128];
__device__ float4 d_b2v[64];

typedef unsigned long long u64;

__device__ __forceinline__ u64 pack2(float lo, float hi) {
    u64 r; asm("mov.b64 %0, {%1, %2};" : "=l"(r) : "f"(lo), "f"(hi)); return r;
}
__device__ __forceinline__ void unpack2(u64 v, float& lo, float& hi) {
    asm("mov.b64 {%0, %1}, %2;" : "=f"(lo), "=f"(hi) : "l"(v));
}
__device__ __forceinline__ u64 fma2(u64 a, u64 b, u64 c) {
    u64 d; asm("fma.rn.f32x2 %0, %1, %2, %3;" : "=l"(d) : "l"(a), "l"(b), "l"(c)); return d;
}
__device__ __forceinline__ float tanhf_(float x) {
    float y; asm("tanh.approx.f32 %0, %1;" : "=f"(y) : "f"(x)); return y;
}
__device__ __forceinline__ float sigmoidf_(float x) {
    return fmaf(0.5f, tanhf_(0.5f * x), 0.5f);
}

// 4 gates x 4 pairs (8 batches), one k
__device__ __forceinline__ void mac4(u64* acc, float4 wv, u64 h0, u64 h1, u64 h2, u64 h3) {
    u64 wi = pack2(wv.x, wv.x), wf = pack2(wv.y, wv.y);
    u64 wg = pack2(wv.z, wv.z), wo = pack2(wv.w, wv.w);
    acc[0]  = fma2(wi, h0, acc[0]);  acc[1]  = fma2(wi, h1, acc[1]);
    acc[2]  = fma2(wi, h2, acc[2]);  acc[3]  = fma2(wi, h3, acc[3]);
    acc[4]  = fma2(wf, h0, acc[4]);  acc[5]  = fma2(wf, h1, acc[5]);
    acc[6]  = fma2(wf, h2, acc[6]);  acc[7]  = fma2(wf, h3, acc[7]);
    acc[8]  = fma2(wg, h0, acc[8]);  acc[9]  = fma2(wg, h1, acc[9]);
    acc[10] = fma2(wg, h2, acc[10]); acc[11] = fma2(wg, h3, acc[11]);
    acc[12] = fma2(wo, h0, acc[12]); acc[13] = fma2(wo, h1, acc[13]);
    acc[14] = fma2(wo, h2, acc[14]); acc[15] = fma2(wo, h3, acc[15]);
}
// 4 gates x 2 pairs (4 batches), one k
__device__ __forceinline__ void mac2(u64* acc, float4 wv, u64 h0, u64 h1) {
    u64 wi = pack2(wv.x, wv.x), wf = pack2(wv.y, wv.y);
    u64 wg = pack2(wv.z, wv.z), wo = pack2(wv.w, wv.w);
    acc[0] = fma2(wi, h0, acc[0]); acc[1] = fma2(wi, h1, acc[1]);
    acc[2] = fma2(wf, h0, acc[2]); acc[3] = fma2(wf, h1, acc[3]);
    acc[4] = fma2(wg, h0, acc[4]); acc[5] = fma2(wg, h1, acc[5]);
    acc[6] = fma2(wo, h0, acc[6]); acc[7] = fma2(wo, h1, acc[7]);
}

__device__ __forceinline__ void acc_init16(u64* acc, float4 bv) {
    u64 bi = pack2(bv.x, bv.x), bf = pack2(bv.y, bv.y);
    u64 bg = pack2(bv.z, bv.z), bo = pack2(bv.w, bv.w);
#pragma unroll
    for (int j = 0; j < 4; j++) { acc[j] = bi; acc[4+j] = bf; acc[8+j] = bg; acc[12+j] = bo; }
}
__device__ __forceinline__ void acc_init8(u64* acc, float4 bv) {
    u64 bi = pack2(bv.x, bv.x), bf = pack2(bv.y, bv.y);
    u64 bg = pack2(bv.z, bv.z), bo = pack2(bv.w, bv.w);
    acc[0] = bi; acc[1] = bi; acc[2] = bf; acc[3] = bf;
    acc[4] = bg; acc[5] = bg; acc[6] = bo; acc[7] = bo;
}

// pointwise: one unit, 8 batches (gates in acc as i,f,g,o x 4 pairs)
__device__ __forceinline__ void pw8(const u64* acc, float* cr, float* dst) {
    float hv[8];
#pragma unroll
    for (int j = 0; j < 4; j++) {
        float i0, i1, f0, f1, g0, g1, o0, o1;
        unpack2(acc[j],    i0, i1); unpack2(acc[4+j],  f0, f1);
        unpack2(acc[8+j],  g0, g1); unpack2(acc[12+j], o0, o1);
        float c0 = sigmoidf_(f0) * cr[2*j]   + sigmoidf_(i0) * tanhf_(g0);
        float c1 = sigmoidf_(f1) * cr[2*j+1] + sigmoidf_(i1) * tanhf_(g1);
        cr[2*j] = c0; cr[2*j+1] = c1;
        hv[2*j]   = sigmoidf_(o0) * tanhf_(c0);
        hv[2*j+1] = sigmoidf_(o1) * tanhf_(c1);
    }
    *(float4*)dst       = make_float4(hv[0], hv[1], hv[2], hv[3]);
    *(float4*)(dst + 4) = make_float4(hv[4], hv[5], hv[6], hv[7]);
}
// pointwise: one unit, 4 batches (gates in acc as i,f,g,o x 2 pairs)
__device__ __forceinline__ void pw4(const u64* acc, float* cr, float* dst) {
    float hv[4];
#pragma unroll
    for (int j = 0; j < 2; j++) {
        float i0, i1, f0, f1, g0, g1, o0, o1;
        unpack2(acc[j],   i0, i1); unpack2(acc[2+j], f0, f1);
        unpack2(acc[4+j], g0, g1); unpack2(acc[6+j], o0, o1);
        float c0 = sigmoidf_(f0) * cr[2*j]   + sigmoidf_(i0) * tanhf_(g0);
        float c1 = sigmoidf_(f1) * cr[2*j+1] + sigmoidf_(i1) * tanhf_(g1);
        cr[2*j] = c0; cr[2*j+1] = c1;
        hv[2*j]   = sigmoidf_(o0) * tanhf_(c0);
        hv[2*j+1] = sigmoidf_(o1) * tanhf_(c1);
    }
    *(float4*)dst = make_float4(hv[0], hv[1], hv[2], hv[3]);
}

// ---- layer 1: thread = unit u (tid&127) x batches 8*bg..8*bg+7 (bg=tid>>7) ----
__device__ __forceinline__ void layer1(float* sm, int u, int bg, int p, float* c1r) {
    u64 acc[16];
    acc_init16(acc, d_b1v[u]);
    const float4* __restrict__ w = d_W1v + u;
    const float* xrow = sm + XB + 8*bg;
#pragma unroll 4
    for (int k = 0; k < NF_; k++) {
        ulonglong2 hA = *(const ulonglong2*)(xrow + k*ROW);
        ulonglong2 hB = *(const ulonglong2*)(xrow + k*ROW + 4);
        mac4(acc, w[k*128], hA.x, hA.y, hB.x, hB.y);
    }
    const float* hrow = sm + H1B + p*2560 + 8*bg;
    const float4* __restrict__ wh = w + NF_*128;
#pragma unroll 4
    for (int k = 0; k < H1_; k++) {
        ulonglong2 hA = *(const ulonglong2*)(hrow + k*ROW);
        ulonglong2 hB = *(const ulonglong2*)(hrow + k*ROW + 4);
        mac4(acc, wh[k*128], hA.x, hA.y, hB.x, hB.y);
    }
    pw8(acc, c1r, sm + H1B + (p^1)*2560 + u*ROW + 8*bg);
}

// ---- layer 2: thread = unit u2 (tid&63) x batches 4*q..4*q+3 (q=tid>>6) ----
__device__ __forceinline__ void layer2(float* sm, int u2, int q, int p, float* c2r) {
    u64 acc[8];
    acc_init8(acc, d_b2v[u2]);
    const float4* __restrict__ w = d_W2v + u2;
    const float* h1n = sm + H1B + (p^1)*2560 + 4*q;
#pragma unroll 4
    for (int k = 0; k < H1_; k++) {
        ulonglong2 hA = *(const ulonglong2*)(h1n + k*ROW);
        mac2(acc, w[k*64], hA.x, hA.y);
    }
    const float* h2r = sm + H2B + p*1280 + 4*q;
#pragma unroll 4
    for (int k = 0; k < H2_; k++) {
        ulonglong2 hA = *(const ulonglong2*)(h2r + k*ROW);
        mac2(acc, w[(H1_+k)*64], hA.x, hA.y);
    }
    pw4(acc, c2r, sm + H2B + (p^1)*1280 + u2*ROW + 4*q);
}

// ---- weight prep ----
__global__ void prep_kernel(const float* __restrict__ Wih1, const float* __restrict__ Whh1,
                            const float* __restrict__ bih1, const float* __restrict__ bhh1,
                            const float* __restrict__ Wih2, const float* __restrict__ Whh2,
                            const float* __restrict__ bih2, const float* __restrict__ bhh2) {
    int idx = blockIdx.x * blockDim.x + threadIdx.x;
    int stride = gridDim.x * blockDim.x;
    for (int i = idx; i < 144*128; i += stride) {
        int k = i >> 7, u = i & 127;
        float4 v;
        if (k < NF_) {
            v = make_float4(Wih1[u*NF_ + k], Wih1[(H1_+u)*NF_ + k],
                            Wih1[(2*H1_+u)*NF_ + k], Wih1[(3*H1_+u)*NF_ + k]);
        } else {
            int kk = k - NF_;
            v = make_float4(Whh1[u*H1_ + kk], Whh1[(H1_+u)*H1_ + kk],
                            Whh1[(2*H1_+u)*H1_ + kk], Whh1[(3*H1_+u)*H1_ + kk]);
        }
        d_W1v[i] = v;
    }
    for (int i = idx; i < 192*64; i += stride) {
        int k = i >> 6, u = i & 63;
        float4 v;
        if (k < H1_) {
            v = make_float4(Wih2[u*H1_ + k], Wih2[(H2_+u)*H1_ + k],
                            Wih2[(2*H2_+u)*H1_ + k], Wih2[(3*H2_+u)*H1_ + k]);
        } else {
            int kk = k - H1_;
            v = make_float4(Whh2[u*H2_ + kk], Whh2[(H2_+u)*H2_ + kk],
                            Whh2[(2*H2_+u)*H2_ + kk], Whh2[(3*H2_+u)*H2_ + kk]);
        }
        d_W2v[i] = v;
    }
    if (idx < H1_)
        d_b1v[idx] = make_float4(bih1[idx] + bhh1[idx], bih1[H1_+idx] + bhh1[H1_+idx],
                                 bih1[2*H1_+idx] + bhh1[2*H1_+idx], bih1[3*H1_+idx] + bhh1[3*H1_+idx]);
    if (idx < H2_)
        d_b2v[idx] = make_float4(bih2[idx] + bhh2[idx], bih2[H2_+idx] + bhh2[H2_+idx],
                                 bih2[2*H2_+idx] + bhh2[2*H2_+idx], bih2[3*H2_+idx] + bhh2[3*H2_+idx]);
}

// ---- main persistent kernel: 2 CTAs per SM ----
__global__ void __launch_bounds__(NTH, 2) lstm_main(
    const float* __restrict__ xh, const float* __restrict__ xfut,
    const float* __restrict__ Wd, const float* __restrict__ bd,
    const float* __restrict__ Wf, const float* __restrict__ bf,
    const float* __restrict__ ob, float* __restrict__ out) {
    extern __shared__ float sm[];
    const int tid = threadIdx.x;
    const int b0  = blockIdx.x * BT_;
    const int u  = tid & 127, bg = tid >> 7;   // layer1 map
    const int u2 = tid & 63,  q  = tid >> 6;   // layer2 map

    for (int i = tid; i < SMF; i += NTH) sm[i] = 0.0f;

    float c1r[8], c2r[4];
#pragma unroll
    for (int j = 0; j < 8; j++) c1r[j] = 0.0f;
#pragma unroll
    for (int j = 0; j < 4; j++) c2r[j] = 0.0f;

    // load x_0 : 16 features x 16 batches
    {
        int f = tid >> 4, bt = tid & 15;
        sm[XB + f*ROW + bt] = xh[(size_t)(b0 + bt) * T_ * NF_ + f];
    }
    __syncthreads();

    int p = 0;
    // ---------- encoder ----------
    for (int t = 0; t < T_; t++) {
        layer1(sm, u, bg, p, c1r);
        __syncthreads();
        layer2(sm, u2, q, p, c2r);
        if (t < T_ - 1) {
            int f = tid >> 4, bt = tid & 15;
            sm[XB + f*ROW + bt] = xh[(size_t)(b0 + bt) * T_ * NF_ + (t+1)*NF_ + f];
        }
        __syncthreads();
        p ^= 1;
    }
    // x rows 14,15 still hold x_{T-1}[14:16] == initial cur

    // refs for st=0
    if (tid < 14 * BT_) {
        int f = tid % 14, bt = tid / 14;
        sm[XB + f*ROW + bt] = xfut[(size_t)(b0 + bt) * S_ * 14 + f];
    }
    __syncthreads();

    // ---------- decoder ----------
    for (int st = 0; st < S_; st++) {
        layer1(sm, u, bg, p, c1r);
        __syncthreads();
        layer2(sm, u2, q, p, c2r);
        if (st < S_ - 1 && tid < 14 * BT_) {
            int f = tid % 14, bt = tid / 14;
            sm[XB + f*ROW + bt] = xfut[(size_t)(b0 + bt) * S_ * 14 + (st+1)*14 + f];
        }
        __syncthreads();

        // dense: DS[bt][du] = relu(h2_new @ Wd^T + bd); du=tid&31, qq=tid>>5 -> bt=qq, qq+8
        {
            int du = tid & 31, qq = tid >> 5;
            const float* h2n = sm + H2B + (p^1)*1280;
            float a0 = 0.f, a1 = 0.f;
#pragma unroll 4
            for (int k = 0; k < H2_; k++) {
                float wv = Wd[du*H2_ + k];
                const float* r = h2n + k*ROW;
                a0 = fmaf(wv, r[qq],     a0);
                a1 = fmaf(wv, r[qq + 8], a1);
            }
            float bdv = bd[du];
            sm[DSO + qq*33 + du]     = fmaxf(a0 + bdv, 0.f);
            sm[DSO + (qq+8)*33 + du] = fmaxf(a1 + bdv, 0.f);
        }
        __syncthreads();

        // pred + feedback
        if (tid < BT_ * NT_) {
            int bt = tid >> 1, tt = tid & 1;
            float acc = 0.f;
#pragma unroll
            for (int k = 0; k < H3_; k++)
                acc = fmaf(sm[DSO + bt*33 + k], Wf[tt*H3_ + k], acc);
            float pr = acc + bf[tt] + ob[tt];
            out[(size_t)(b0 + bt) * S_ * NT_ + st * NT_ + tt] = pr;
            sm[XB + (NF_ - NT_ + tt)*ROW + bt] = pr;
        }
        __syncthreads();
        p ^= 1;
    }
}

// ---- launch ----
extern "C" void kernel_launch(void* const* d_in, const int* in_sizes, int n_in,
                              void* d_out, int out_size) {
    (void)in_sizes; (void)n_in; (void)out_size;
    const float* xh   = (const float*)d_in[0];
    const float* xfut = (const float*)d_in[1];
    const float* Wih1 = (const float*)d_in[2];
    const float* Whh1 = (const float*)d_in[3];
    const float* bih1 = (const float*)d_in[4];
    const float* bhh1 = (const float*)d_in[5];
    const float* Wih2 = (const float*)d_in[6];
    const float* Whh2 = (const float*)d_in[7];
    const float* bih2 = (const float*)d_in[8];
    const float* bhh2 = (const float*)d_in[9];
    const float* Wd   = (const float*)d_in[10];
    const float* bd   = (const float*)d_in[11];
    const float* Wf   = (const float*)d_in[12];
    const float* bf   = (const float*)d_in[13];
    const float* ob   = (const float*)d_in[14];
    float* out = (float*)d_out;

    cudaFuncSetAttribute(lstm_main, cudaFuncAttributeMaxDynamicSharedMemorySize, SMB);
    prep_kernel<<<128, 256>>>(Wih1, Whh1, bih1, bhh1, Wih2, Whh2, bih2, bhh2);
    lstm_main<<<NBLK, NTH, SMB>>>(xh, xfut, Wd, bd, Wf, bf, ob, out);
}